// round 13
// baseline (speedup 1.0000x reference)
#include <cuda_runtime.h>
#include <cuda_fp16.h>
#include <cstdint>

// Problem constants
#define B_   2
#define S_   2048
#define E_   1024
#define H_   16
#define HD_  64
#define M_   (B_ * S_)   // 4096 flattened rows

// Scratch (fp16)
__device__ __half g_qc[M_ * E_];
__device__ __half g_kc[M_ * E_];
__device__ __half g_vc[M_ * E_];
__device__ __half g_wc[4 * E_ * E_];
__device__ __half g_qh[M_ * E_];
__device__ __half g_kh[M_ * E_];
__device__ __half g_vh[M_ * E_];
__device__ __half g_ah[M_ * E_];

// ===========================================================================
// Helpers
// ===========================================================================
__device__ __forceinline__ uint32_t smem_u32(const void* p) {
    uint32_t a;
    asm("{ .reg .u64 t; cvta.to.shared.u64 t, %1; cvt.u32.u64 %0, t; }"
        : "=r"(a) : "l"(p));
    return a;
}

__device__ __forceinline__ void cp_async16(uint32_t dst, const void* src) {
    asm volatile("cp.async.cg.shared.global [%0], [%1], 16;"
                 :: "r"(dst), "l"(src) : "memory");
}
#define CP_COMMIT() asm volatile("cp.async.commit_group;" ::: "memory")
#define CP_WAIT1()  asm volatile("cp.async.wait_group 1;" ::: "memory")

__device__ __forceinline__ void mma_f16(float* d, const uint32_t* a, const uint32_t* b) {
    asm volatile(
        "mma.sync.aligned.m16n8k16.row.col.f32.f16.f16.f32 "
        "{%0,%1,%2,%3}, {%4,%5,%6,%7}, {%8,%9}, {%0,%1,%2,%3};"
        : "+f"(d[0]), "+f"(d[1]), "+f"(d[2]), "+f"(d[3])
        : "r"(a[0]), "r"(a[1]), "r"(a[2]), "r"(a[3]), "r"(b[0]), "r"(b[1]));
}

__device__ __forceinline__ void ldsm4(uint32_t* r, uint32_t addr) {
    asm volatile("ldmatrix.sync.aligned.m8n8.x4.shared.b16 {%0,%1,%2,%3}, [%4];"
                 : "=r"(r[0]), "=r"(r[1]), "=r"(r[2]), "=r"(r[3]) : "r"(addr));
}
__device__ __forceinline__ void ldsm4t(uint32_t* r, uint32_t addr) {
    asm volatile("ldmatrix.sync.aligned.m8n8.x4.trans.shared.b16 {%0,%1,%2,%3}, [%4];"
                 : "=r"(r[0]), "=r"(r[1]), "=r"(r[2]), "=r"(r[3]) : "r"(addr));
}

__device__ __forceinline__ uint32_t h2pack(float a, float b) {
    __half2 h = __floats2half2_rn(a, b);
    return *(uint32_t*)&h;
}

// ===========================================================================
// fp32 -> fp16 conversion prepass (one launch; groups of 8 floats)
// ===========================================================================
#define ACT8 (M_ * E_ / 8)
#define W8   (E_ * E_ / 8)
#define TOT8 (3 * ACT8 + 4 * W8)

__global__ __launch_bounds__(256) void round_h_all(
    const float4* __restrict__ q, const float4* __restrict__ k,
    const float4* __restrict__ v,
    const float4* __restrict__ Wq, const float4* __restrict__ Wk,
    const float4* __restrict__ Wv, const float4* __restrict__ Wo,
    __half* __restrict__ qc, __half* __restrict__ kc,
    __half* __restrict__ vc, __half* __restrict__ wc)
{
    const long i = (long)blockIdx.x * 256 + threadIdx.x;
    if (i >= TOT8) return;
    const float4* s; __half* d; long off;
    if (i < ACT8)            { s = q; d = qc; off = i; }
    else if (i < 2L * ACT8)  { s = k; d = kc; off = i - ACT8; }
    else if (i < 3L * ACT8)  { s = v; d = vc; off = i - 2L * ACT8; }
    else {
        const long j = i - 3L * ACT8;
        s = (j < W8) ? Wq : (j < 2 * W8) ? Wk : (j < 3 * W8) ? Wv : Wo;
        d = wc + (j / W8) * (E_ * (long)E_);
        off = j % W8;
    }
    float4 u = s[2 * off], w = s[2 * off + 1];
    uint4 o;
    o.x = h2pack(u.x, u.y); o.y = h2pack(u.z, u.w);
    o.z = h2pack(w.x, w.y); o.w = h2pack(w.z, w.w);
    *(uint4*)(d + off * 8) = o;
}

// ===========================================================================
// Templated fp16 mma GEMM: C[M,1024] = A[M,1024] @ W[1024,1024]^T (+ bias)
// TMt x TNt CTA tile, 4 warps (MW x NW), K-chunk 64 halves, 2-stage double
// buffer, ldmatrix.x4. fp32 accumulate; output fp16 (Ch) or fp32 (Cf).
// ===========================================================================
#define GTK   64
#define NCH   (E_ / GTK)                  // 16
#define ROWB  144                          // 64 halves + 16B pad

template<int TMt, int TNt, int MW, int NW, int MINB>
__global__ __launch_bounds__(128, MINB) void gemm_t(
    const __half* __restrict__ A0, const __half* __restrict__ A1,
    const __half* __restrict__ A2,
    const __half* __restrict__ W0, const __half* __restrict__ W1,
    const __half* __restrict__ W2,
    float* __restrict__ Cf,
    __half* __restrict__ Ch0, __half* __restrict__ Ch1, __half* __restrict__ Ch2,
    const float* __restrict__ b0, const float* __restrict__ b1,
    const float* __restrict__ b2)
{
    constexpr int MI  = TMt / MW / 16;     // m16 frags per warp
    constexpr int JP  = TNt / NW / 16;     // n16 ldsm groups per warp
    constexpr int STG = (TMt + TNt) * ROWB;

    extern __shared__ char smem[];
    const int tid  = threadIdx.x;
    const int lane = tid & 31;
    const int wid  = tid >> 5;
    const int wm   = wid % MW;
    const int wn   = wid / MW;

    const int z = blockIdx.z;
    const __half* A = (z == 0) ? A0 : (z == 1) ? A1 : A2;
    const __half* W = (z == 0) ? W0 : (z == 1) ? W1 : W2;
    __half* Ch = (z == 0) ? Ch0 : (z == 1) ? Ch1 : Ch2;
    const float* bias = (z == 0) ? b0 : (z == 1) ? b1 : b2;

    const int m0 = blockIdx.x * TMt;
    const int n0 = blockIdx.y * TNt;
    const uint32_t sb = smem_u32(smem);

    uint32_t aoff[MI], boff[JP];
    #pragma unroll
    for (int ii = 0; ii < MI; ii++)
        aoff[ii] = (wm * (TMt / MW) + ii * 16 + (lane & 15)) * ROWB
                 + (lane >> 4) * 16;
    #pragma unroll
    for (int jp = 0; jp < JP; jp++)
        boff[jp] = TMt * ROWB
                 + (wn * (TNt / NW) + jp * 16 + ((lane >> 4) << 3) + (lane & 7)) * ROWB
                 + ((lane >> 3) & 1) * 16;

    float acc[MI][2 * JP][4] = {};

    auto load_chunk = [&](int ch, int stg) {
        const int k0 = ch * GTK;
        const uint32_t as = sb + stg * STG;
        const uint32_t bs = as + TMt * ROWB;
        #pragma unroll
        for (int it = 0; it < TMt / 16; it++) {
            const int idx = tid + it * 128;
            const int r = idx >> 3, c8 = idx & 7;
            cp_async16(as + r * ROWB + c8 * 16,
                       A + (size_t)(m0 + r) * E_ + k0 + c8 * 8);
        }
        #pragma unroll
        for (int it = 0; it < TNt / 16; it++) {
            const int idx = tid + it * 128;
            const int r = idx >> 3, c8 = idx & 7;
            cp_async16(bs + r * ROWB + c8 * 16,
                       W + (size_t)(n0 + r) * E_ + k0 + c8 * 8);
        }
    };

    load_chunk(0, 0); CP_COMMIT();

    for (int i = 0; i < NCH; i++) {
        if (i + 1 < NCH) load_chunk(i + 1, (i + 1) & 1);
        CP_COMMIT();               // commit (possibly empty) to keep accounting
        CP_WAIT1();                // load(i) complete
        __syncthreads();

        const uint32_t su = sb + (i & 1) * STG;
        #pragma unroll
        for (int kk = 0; kk < 4; kk++) {
            const uint32_t kb = su + kk * 32;
            uint32_t af[MI][4], bf[JP][4];
            #pragma unroll
            for (int ii = 0; ii < MI; ii++) ldsm4(af[ii], kb + aoff[ii]);
            #pragma unroll
            for (int jp = 0; jp < JP; jp++) ldsm4(bf[jp], kb + boff[jp]);
            #pragma unroll
            for (int ii = 0; ii < MI; ii++)
                #pragma unroll
                for (int jp = 0; jp < JP; jp++) {
                    mma_f16(acc[ii][2 * jp],     af[ii], &bf[jp][0]);
                    mma_f16(acc[ii][2 * jp + 1], af[ii], &bf[jp][2]);
                }
        }
        __syncthreads();           // protect this stage before iter i+1 reloads it
    }

    const int g = lane >> 2;
    const int c = lane & 3;
    #pragma unroll
    for (int ii = 0; ii < MI; ii++) {
        const int r0 = m0 + wm * (TMt / MW) + ii * 16 + g;
        #pragma unroll
        for (int jj = 0; jj < 2 * JP; jj++) {
            const int cc = n0 + wn * (TNt / NW) + jj * 8 + 2 * c;
            float bx = 0.f, by = 0.f;
            if (bias) { bx = bias[cc]; by = bias[cc + 1]; }
            const float v00 = acc[ii][jj][0] + bx, v01 = acc[ii][jj][1] + by;
            const float v10 = acc[ii][jj][2] + bx, v11 = acc[ii][jj][3] + by;
            if (Ch) {
                *(uint32_t*)&Ch[(size_t)r0 * E_ + cc]       = h2pack(v00, v01);
                *(uint32_t*)&Ch[(size_t)(r0 + 8) * E_ + cc] = h2pack(v10, v11);
            } else {
                *(float2*)&Cf[(size_t)r0 * E_ + cc]       = make_float2(v00, v01);
                *(float2*)&Cf[(size_t)(r0 + 8) * E_ + cc] = make_float2(v10, v11);
            }
        }
    }
}

// QKV: 128x64 tiles, warps 4x1 (32x64), 4 CTAs/SM, smem 55296 (221 KB total)
// Wo:  64x64 tiles,  warps 2x2 (32x32), 4 CTAs/SM, smem 36864
#define QKV_SMEM (2 * (128 + 64) * ROWB)
#define WO_SMEM  (2 * (64 + 64) * ROWB)

// ===========================================================================
// fp16 tensor-core flash attention, strict-causal with (0,0) exception.
// CTA = (b,h) x 64 q-rows; 4 warps x 16 rows; K/V blocks of 64; 3 CTAs/SM.
// (unchanged from R11/R12)
// ===========================================================================
#define AQ    64
#define AK    64
#define QBYTES (AQ * 144)
#define KVBYTES (AK * 144)
#define OFF_K  QBYTES
#define OFF_V  (OFF_K + 2 * KVBYTES)
#define ATTN_SMEM (OFF_V + 2 * KVBYTES)       // 46080

__global__ __launch_bounds__(128, 3) void attn_mma(
    const __half* __restrict__ QH, const __half* __restrict__ KH,
    const __half* __restrict__ VH, __half* __restrict__ AH)
{
    extern __shared__ char smc[];
    const int tid  = threadIdx.x;
    const int lane = tid & 31;
    const int w    = tid >> 5;
    const int g    = lane >> 2;
    const int c    = lane & 3;
    const int qi   = (int)(gridDim.x - 1) - (int)blockIdx.x;  // heavy tiles first
    const int bh   = blockIdx.y;
    const int b    = bh >> 4;
    const int h    = bh & 15;
    const int qbase = qi * AQ;
    const size_t rb = (size_t)b * S_ * E_ + (size_t)h * HD_;

    const uint32_t sb = smem_u32(smc);

    #pragma unroll
    for (int it = 0; it < 4; it++) {
        const int idx = tid + it * 128;
        const int r = idx >> 3, c8 = idx & 7;
        uint4 v = *(const uint4*)&QH[rb + (size_t)(qbase + r) * E_ + c8 * 8];
        *(uint4*)(smc + r * 144 + c8 * 16) = v;
    }
    __syncthreads();

    uint32_t qf[4][4];
    #pragma unroll
    for (int kk = 0; kk < 4; kk++)
        ldsm4(qf[kk], sb + (w * 16 + (lane & 15)) * 144 + kk * 32 + (lane >> 4) * 16);
    __syncthreads();

    float o[8][4] = {};
    float m0 = -1e30f, m1 = -1e30f, l0 = 0.f, l1 = 0.f;
    const int nb = qi + 1;
    const int qrow0 = qbase + w * 16 + g;
    const int wmin  = qbase + w * 16;

    uint32_t koff[4], voff[4];
    #pragma unroll
    for (int jp = 0; jp < 4; jp++)
        koff[jp] = (jp * 16 + ((lane >> 4) << 3) + (lane & 7)) * 144
                 + ((lane >> 3) & 1) * 16;
    {
        const int qd = lane >> 3;
        #pragma unroll
        for (int jp = 0; jp < 4; jp++)
            voff[jp] = (((qd & 1) << 3) + (lane & 7)) * 144
                     + jp * 32 + ((qd >> 1) << 4);
    }

    auto loadKV = [&](int kb, int stg) {
        const int t0 = kb * AK;
        const uint32_t ks = sb + OFF_K + stg * KVBYTES;
        const uint32_t vs = sb + OFF_V + stg * KVBYTES;
        #pragma unroll
        for (int it = 0; it < 4; it++) {
            const int idx = tid + it * 128;
            const int r = idx >> 3, c8 = idx & 7;
            cp_async16(ks + r * 144 + c8 * 16,
                       &KH[rb + (size_t)(t0 + r) * E_ + c8 * 8]);
            cp_async16(vs + r * 144 + c8 * 16,
                       &VH[rb + (size_t)(t0 + r) * E_ + c8 * 8]);
        }
    };

    loadKV(0, 0); CP_COMMIT();

    for (int kb = 0; kb < nb; kb++) {
        const int stg = kb & 1;
        const int t0  = kb * AK;
        if (kb + 1 < nb) loadKV(kb + 1, stg ^ 1);
        CP_COMMIT();
        CP_WAIT1();
        __syncthreads();

        {
            const uint32_t ks = sb + OFF_K + stg * KVBYTES;
            const uint32_t vs = sb + OFF_V + stg * KVBYTES;

            float sc[8][4] = {};
            #pragma unroll
            for (int kk = 0; kk < 4; kk++) {
                uint32_t kf[4][4];
                #pragma unroll
                for (int jp = 0; jp < 4; jp++) ldsm4(kf[jp], ks + koff[jp] + kk * 32);
                #pragma unroll
                for (int jp = 0; jp < 4; jp++) {
                    mma_f16(sc[2 * jp],     qf[kk], &kf[jp][0]);
                    mma_f16(sc[2 * jp + 1], qf[kk], &kf[jp][2]);
                }
            }

            const bool needmask = (t0 + AK - 1) >= wmin;
            #pragma unroll
            for (int jj = 0; jj < 8; jj++) {
                sc[jj][0] *= 0.125f; sc[jj][1] *= 0.125f;
                sc[jj][2] *= 0.125f; sc[jj][3] *= 0.125f;
                if (needmask) {
                    const int cg = t0 + jj * 8 + 2 * c;
                    const int r0 = qrow0, r1 = qrow0 + 8;
                    if (!((cg     < r0) || (r0 == 0 && cg == 0)))     sc[jj][0] = -1e30f;
                    if (!((cg + 1 < r0) || (r0 == 0 && cg + 1 == 0))) sc[jj][1] = -1e30f;
                    if (!(cg     < r1)) sc[jj][2] = -1e30f;
                    if (!(cg + 1 < r1)) sc[jj][3] = -1e30f;
                }
            }

            float mx0 = -1e30f, mx1 = -1e30f;
            #pragma unroll
            for (int jj = 0; jj < 8; jj++) {
                mx0 = fmaxf(mx0, fmaxf(sc[jj][0], sc[jj][1]));
                mx1 = fmaxf(mx1, fmaxf(sc[jj][2], sc[jj][3]));
            }
            mx0 = fmaxf(mx0, __shfl_xor_sync(0xffffffffu, mx0, 1));
            mx0 = fmaxf(mx0, __shfl_xor_sync(0xffffffffu, mx0, 2));
            mx1 = fmaxf(mx1, __shfl_xor_sync(0xffffffffu, mx1, 1));
            mx1 = fmaxf(mx1, __shfl_xor_sync(0xffffffffu, mx1, 2));
            const float mn0 = fmaxf(m0, mx0), mn1 = fmaxf(m1, mx1);
            const float a0 = __expf(m0 - mn0), a1 = __expf(m1 - mn1);
            float s0 = 0.f, s1 = 0.f;
            #pragma unroll
            for (int jj = 0; jj < 8; jj++) {
                sc[jj][0] = __expf(sc[jj][0] - mn0);
                sc[jj][1] = __expf(sc[jj][1] - mn0);
                sc[jj][2] = __expf(sc[jj][2] - mn1);
                sc[jj][3] = __expf(sc[jj][3] - mn1);
                s0 += sc[jj][0] + sc[jj][1];
                s1 += sc[jj][2] + sc[jj][3];
            }
            s0 += __shfl_xor_sync(0xffffffffu, s0, 1);
            s0 += __shfl_xor_sync(0xffffffffu, s0, 2);
            s1 += __shfl_xor_sync(0xffffffffu, s1, 1);
            s1 += __shfl_xor_sync(0xffffffffu, s1, 2);
            l0 = l0 * a0 + s0; l1 = l1 * a1 + s1;
            m0 = mn0; m1 = mn1;
            #pragma unroll
            for (int jj = 0; jj < 8; jj++) {
                o[jj][0] *= a0; o[jj][1] *= a0;
                o[jj][2] *= a1; o[jj][3] *= a1;
            }

            #pragma unroll
            for (int kk = 0; kk < 4; kk++) {
                uint32_t pf[4];
                pf[0] = h2pack(sc[2 * kk][0],     sc[2 * kk][1]);
                pf[1] = h2pack(sc[2 * kk][2],     sc[2 * kk][3]);
                pf[2] = h2pack(sc[2 * kk + 1][0], sc[2 * kk + 1][1]);
                pf[3] = h2pack(sc[2 * kk + 1][2], sc[2 * kk + 1][3]);
                uint32_t vf[4][4];
                #pragma unroll
                for (int jp = 0; jp < 4; jp++)
                    ldsm4t(vf[jp], vs + voff[jp] + kk * 16 * 144);
                #pragma unroll
                for (int jp = 0; jp < 4; jp++) {
                    mma_f16(o[2 * jp],     pf, &vf[jp][0]);
                    mma_f16(o[2 * jp + 1], pf, &vf[jp][2]);
                }
            }
        }
        __syncthreads();
    }

    const float il0 = 1.f / l0, il1 = 1.f / l1;
    #pragma unroll
    for (int jj = 0; jj < 8; jj++) {
        const int col = jj * 8 + 2 * c;
        *(uint32_t*)&AH[rb + (size_t)qrow0 * E_ + col] =
            h2pack(o[jj][0] * il0, o[jj][1] * il0);
        *(uint32_t*)&AH[rb + (size_t)(qrow0 + 8) * E_ + col] =
            h2pack(o[jj][2] * il1, o[jj][3] * il1);
    }
}

// ===========================================================================
extern "C" void kernel_launch(void* const* d_in, const int* in_sizes, int n_in,
                              void* d_out, int out_size)
{
    const float* q  = (const float*)d_in[0];
    const float* k  = (const float*)d_in[1];
    const float* v  = (const float*)d_in[2];
    const float* Wq = (const float*)d_in[3];
    const float* Wk = (const float*)d_in[4];
    const float* Wv = (const float*)d_in[5];
    const float* bv = (const float*)d_in[6];
    const float* Wo = (const float*)d_in[7];
    const float* bo = (const float*)d_in[8];
    float* out = (float*)d_out;

    __half *qc, *kc, *vc, *wc, *qh, *kh, *vh, *ah;
    cudaGetSymbolAddress((void**)&qc, g_qc);
    cudaGetSymbolAddress((void**)&kc, g_kc);
    cudaGetSymbolAddress((void**)&vc, g_vc);
    cudaGetSymbolAddress((void**)&wc, g_wc);
    cudaGetSymbolAddress((void**)&qh, g_qh);
    cudaGetSymbolAddress((void**)&kh, g_kh);
    cudaGetSymbolAddress((void**)&vh, g_vh);
    cudaGetSymbolAddress((void**)&ah, g_ah);

    auto* gemm_qkv = gemm_t<128, 64, 4, 1, 4>;   // 4 CTAs/SM (was 3)
    auto* gemm_wo  = gemm_t<64, 64, 2, 2, 4>;
    cudaFuncSetAttribute(gemm_qkv, cudaFuncAttributeMaxDynamicSharedMemorySize,
                         QKV_SMEM);
    cudaFuncSetAttribute(gemm_wo, cudaFuncAttributeMaxDynamicSharedMemorySize,
                         WO_SMEM);
    cudaFuncSetAttribute(attn_mma, cudaFuncAttributeMaxDynamicSharedMemorySize,
                         ATTN_SMEM);

    // ---- fp16 conversion prepass (one launch) ----
    round_h_all<<<(TOT8 + 255) / 256, 256>>>(
        (const float4*)q, (const float4*)k, (const float4*)v,
        (const float4*)Wq, (const float4*)Wk, (const float4*)Wv, (const float4*)Wo,
        qc, kc, vc, wc);

    // ---- fused Q/K/V projections: 128x64 tiles (fp16 out) ----
    const dim3 gqkv(M_ / 128, E_ / 64, 3);     // (32, 16, 3) = 1536 tiles
    gemm_qkv<<<gqkv, 128, QKV_SMEM>>>(qc, kc, vc,
                                      wc, wc + (size_t)E_ * E_, wc + 2 * (size_t)E_ * E_,
                                      nullptr,
                                      qh, kh, vh,
                                      nullptr, nullptr, bv);

    // ---- attention (AQ=64, 3 CTAs/SM) ----
    const dim3 agrd(S_ / AQ, B_ * H_);         // (32, 32)
    attn_mma<<<agrd, 128, ATTN_SMEM>>>(qh, kh, vh, ah);

    // ---- output projection: 64x64 tiles (fp32 out + bias) ----
    const dim3 gwo(M_ / 64, E_ / 64, 1);       // (64, 16) = 1024 tiles
    gemm_wo<<<gwo, 128, WO_SMEM>>>(ah, ah, ah,
                                   wc + 3 * (size_t)E_ * E_, nullptr, nullptr,
                                   out,
                                   nullptr, nullptr, nullptr,
                                   bo, bo, bo);
}

// round 14
// speedup vs baseline: 1.0241x; 1.0241x over previous
#include <cuda_runtime.h>
#include <cuda_fp16.h>
#include <cstdint>

// Problem constants
#define B_   2
#define S_   2048
#define E_   1024
#define H_   16
#define HD_  64
#define M_   (B_ * S_)   // 4096 flattened rows

// Scratch (fp16)
__device__ __half g_qc[M_ * E_];
__device__ __half g_kc[M_ * E_];
__device__ __half g_vc[M_ * E_];
__device__ __half g_wc[4 * E_ * E_];
__device__ __half g_qh[M_ * E_];
__device__ __half g_kh[M_ * E_];
__device__ __half g_vh[M_ * E_];
__device__ __half g_ah[M_ * E_];

// ===========================================================================
// Helpers
// ===========================================================================
__device__ __forceinline__ uint32_t smem_u32(const void* p) {
    uint32_t a;
    asm("{ .reg .u64 t; cvta.to.shared.u64 t, %1; cvt.u32.u64 %0, t; }"
        : "=r"(a) : "l"(p));
    return a;
}

__device__ __forceinline__ void cp_async16(uint32_t dst, const void* src) {
    asm volatile("cp.async.cg.shared.global [%0], [%1], 16;"
                 :: "r"(dst), "l"(src) : "memory");
}
#define CP_COMMIT() asm volatile("cp.async.commit_group;" ::: "memory")
#define CP_WAIT0()  asm volatile("cp.async.wait_group 0;" ::: "memory")

__device__ __forceinline__ void mma_f16(float* d, const uint32_t* a, const uint32_t* b) {
    asm volatile(
        "mma.sync.aligned.m16n8k16.row.col.f32.f16.f16.f32 "
        "{%0,%1,%2,%3}, {%4,%5,%6,%7}, {%8,%9}, {%0,%1,%2,%3};"
        : "+f"(d[0]), "+f"(d[1]), "+f"(d[2]), "+f"(d[3])
        : "r"(a[0]), "r"(a[1]), "r"(a[2]), "r"(a[3]), "r"(b[0]), "r"(b[1]));
}

__device__ __forceinline__ void ldsm4(uint32_t* r, uint32_t addr) {
    asm volatile("ldmatrix.sync.aligned.m8n8.x4.shared.b16 {%0,%1,%2,%3}, [%4];"
                 : "=r"(r[0]), "=r"(r[1]), "=r"(r[2]), "=r"(r[3]) : "r"(addr));
}
__device__ __forceinline__ void ldsm4t(uint32_t* r, uint32_t addr) {
    asm volatile("ldmatrix.sync.aligned.m8n8.x4.trans.shared.b16 {%0,%1,%2,%3}, [%4];"
                 : "=r"(r[0]), "=r"(r[1]), "=r"(r[2]), "=r"(r[3]) : "r"(addr));
}

__device__ __forceinline__ uint32_t h2pack(float a, float b) {
    __half2 h = __floats2half2_rn(a, b);
    return *(uint32_t*)&h;
}

// ===========================================================================
// fp32 -> fp16 conversion prepass (one launch; groups of 8 floats)
// ===========================================================================
#define ACT8 (M_ * E_ / 8)
#define W8   (E_ * E_ / 8)
#define TOT8 (3 * ACT8 + 4 * W8)

__global__ __launch_bounds__(256) void round_h_all(
    const float4* __restrict__ q, const float4* __restrict__ k,
    const float4* __restrict__ v,
    const float4* __restrict__ Wq, const float4* __restrict__ Wk,
    const float4* __restrict__ Wv, const float4* __restrict__ Wo,
    __half* __restrict__ qc, __half* __restrict__ kc,
    __half* __restrict__ vc, __half* __restrict__ wc)
{
    const long i = (long)blockIdx.x * 256 + threadIdx.x;
    if (i >= TOT8) return;
    const float4* s; __half* d; long off;
    if (i < ACT8)            { s = q; d = qc; off = i; }
    else if (i < 2L * ACT8)  { s = k; d = kc; off = i - ACT8; }
    else if (i < 3L * ACT8)  { s = v; d = vc; off = i - 2L * ACT8; }
    else {
        const long j = i - 3L * ACT8;
        s = (j < W8) ? Wq : (j < 2 * W8) ? Wk : (j < 3 * W8) ? Wv : Wo;
        d = wc + (j / W8) * (E_ * (long)E_);
        off = j % W8;
    }
    float4 u = s[2 * off], w = s[2 * off + 1];
    uint4 o;
    o.x = h2pack(u.x, u.y); o.y = h2pack(u.z, u.w);
    o.z = h2pack(w.x, w.y); o.w = h2pack(w.z, w.w);
    *(uint4*)(d + off * 8) = o;
}

// ===========================================================================
// Templated fp16 mma GEMM: C[M,1024] = A[M,1024] @ W[1024,1024]^T (+ bias)
// TMt x TNt CTA tile, 4 warps (MW x NW), K-chunk 64 halves, single-sync
// 2-stage double buffer, ldmatrix.x4. fp32 accumulate.
// ===========================================================================
#define GTK   64
#define NCH   (E_ / GTK)                  // 16
#define ROWB  144                          // 64 halves + 16B pad

template<int TMt, int TNt, int MW, int NW, int MINB>
__global__ __launch_bounds__(128, MINB) void gemm_t(
    const __half* __restrict__ A0, const __half* __restrict__ A1,
    const __half* __restrict__ A2,
    const __half* __restrict__ W0, const __half* __restrict__ W1,
    const __half* __restrict__ W2,
    float* __restrict__ Cf,
    __half* __restrict__ Ch0, __half* __restrict__ Ch1, __half* __restrict__ Ch2,
    const float* __restrict__ b0, const float* __restrict__ b1,
    const float* __restrict__ b2)
{
    constexpr int MI  = TMt / MW / 16;     // m16 frags per warp
    constexpr int JP  = TNt / NW / 16;     // n16 ldsm groups per warp
    constexpr int STG = (TMt + TNt) * ROWB;

    extern __shared__ char smem[];
    const int tid  = threadIdx.x;
    const int lane = tid & 31;
    const int wid  = tid >> 5;
    const int wm   = wid % MW;
    const int wn   = wid / MW;

    const int z = blockIdx.z;
    const __half* A = (z == 0) ? A0 : (z == 1) ? A1 : A2;
    const __half* W = (z == 0) ? W0 : (z == 1) ? W1 : W2;
    __half* Ch = (z == 0) ? Ch0 : (z == 1) ? Ch1 : Ch2;
    const float* bias = (z == 0) ? b0 : (z == 1) ? b1 : b2;

    const int m0 = blockIdx.x * TMt;
    const int n0 = blockIdx.y * TNt;
    const uint32_t sb = smem_u32(smem);

    uint32_t aoff[MI], boff[JP];
    #pragma unroll
    for (int ii = 0; ii < MI; ii++)
        aoff[ii] = (wm * (TMt / MW) + ii * 16 + (lane & 15)) * ROWB
                 + (lane >> 4) * 16;
    #pragma unroll
    for (int jp = 0; jp < JP; jp++)
        boff[jp] = TMt * ROWB
                 + (wn * (TNt / NW) + jp * 16 + ((lane >> 4) << 3) + (lane & 7)) * ROWB
                 + ((lane >> 3) & 1) * 16;

    float acc[MI][2 * JP][4] = {};

    auto load_chunk = [&](int ch, int stg) {
        const int k0 = ch * GTK;
        const uint32_t as = sb + stg * STG;
        const uint32_t bs = as + TMt * ROWB;
        #pragma unroll
        for (int it = 0; it < TMt / 16; it++) {
            const int idx = tid + it * 128;
            const int r = idx >> 3, c8 = idx & 7;
            cp_async16(as + r * ROWB + c8 * 16,
                       A + (size_t)(m0 + r) * E_ + k0 + c8 * 8);
        }
        #pragma unroll
        for (int it = 0; it < TNt / 16; it++) {
            const int idx = tid + it * 128;
            const int r = idx >> 3, c8 = idx & 7;
            cp_async16(bs + r * ROWB + c8 * 16,
                       W + (size_t)(n0 + r) * E_ + k0 + c8 * 8);
        }
    };

    load_chunk(0, 0); CP_COMMIT();

    for (int i = 0; i < NCH; i++) {
        CP_WAIT0();                // load(i) landed (only outstanding group)
        __syncthreads();           // + everyone done computing stage (i+1)&1
        if (i + 1 < NCH) { load_chunk(i + 1, (i + 1) & 1); CP_COMMIT(); }

        const uint32_t su = sb + (i & 1) * STG;
        #pragma unroll
        for (int kk = 0; kk < 4; kk++) {
            const uint32_t kb = su + kk * 32;
            uint32_t af[MI][4], bf[JP][4];
            #pragma unroll
            for (int ii = 0; ii < MI; ii++) ldsm4(af[ii], kb + aoff[ii]);
            #pragma unroll
            for (int jp = 0; jp < JP; jp++) ldsm4(bf[jp], kb + boff[jp]);
            #pragma unroll
            for (int ii = 0; ii < MI; ii++)
                #pragma unroll
                for (int jp = 0; jp < JP; jp++) {
                    mma_f16(acc[ii][2 * jp],     af[ii], &bf[jp][0]);
                    mma_f16(acc[ii][2 * jp + 1], af[ii], &bf[jp][2]);
                }
        }
    }

    const int g = lane >> 2;
    const int c = lane & 3;
    #pragma unroll
    for (int ii = 0; ii < MI; ii++) {
        const int r0 = m0 + wm * (TMt / MW) + ii * 16 + g;
        #pragma unroll
        for (int jj = 0; jj < 2 * JP; jj++) {
            const int cc = n0 + wn * (TNt / NW) + jj * 8 + 2 * c;
            float bx = 0.f, by = 0.f;
            if (bias) { bx = bias[cc]; by = bias[cc + 1]; }
            const float v00 = acc[ii][jj][0] + bx, v01 = acc[ii][jj][1] + by;
            const float v10 = acc[ii][jj][2] + bx, v11 = acc[ii][jj][3] + by;
            if (Ch) {
                *(uint32_t*)&Ch[(size_t)r0 * E_ + cc]       = h2pack(v00, v01);
                *(uint32_t*)&Ch[(size_t)(r0 + 8) * E_ + cc] = h2pack(v10, v11);
            } else {
                *(float2*)&Cf[(size_t)r0 * E_ + cc]       = make_float2(v00, v01);
                *(float2*)&Cf[(size_t)(r0 + 8) * E_ + cc] = make_float2(v10, v11);
            }
        }
    }
}

// QKV: 128x64 tiles, warps 4x1 (32x64), 3 CTAs/SM, smem 55296
// Wo:  64x64 tiles,  warps 2x2 (32x32), 4 CTAs/SM, smem 36864
#define QKV_SMEM (2 * (128 + 64) * ROWB)
#define WO_SMEM  (2 * (64 + 64) * ROWB)

// ===========================================================================
// fp16 tensor-core flash attention, strict-causal with (0,0) exception.
// CTA = (b,h) x 64 q-rows; 4 warps x 16 rows; K/V blocks of 64; 3 CTAs/SM.
// Single-sync pipeline.
// ===========================================================================
#define AQ    64
#define AK    64
#define QBYTES (AQ * 144)
#define KVBYTES (AK * 144)
#define OFF_K  QBYTES
#define OFF_V  (OFF_K + 2 * KVBYTES)
#define ATTN_SMEM (OFF_V + 2 * KVBYTES)       // 46080

__global__ __launch_bounds__(128, 3) void attn_mma(
    const __half* __restrict__ QH, const __half* __restrict__ KH,
    const __half* __restrict__ VH, __half* __restrict__ AH)
{
    extern __shared__ char smc[];
    const int tid  = threadIdx.x;
    const int lane = tid & 31;
    const int w    = tid >> 5;
    const int g    = lane >> 2;
    const int c    = lane & 3;
    const int qi   = (int)(gridDim.x - 1) - (int)blockIdx.x;  // heavy tiles first
    const int bh   = blockIdx.y;
    const int b    = bh >> 4;
    const int h    = bh & 15;
    const int qbase = qi * AQ;
    const size_t rb = (size_t)b * S_ * E_ + (size_t)h * HD_;

    const uint32_t sb = smem_u32(smc);

    // ---- load Q tile (64 x 64 halves) ----
    #pragma unroll
    for (int it = 0; it < 4; it++) {
        const int idx = tid + it * 128;
        const int r = idx >> 3, c8 = idx & 7;
        uint4 v = *(const uint4*)&QH[rb + (size_t)(qbase + r) * E_ + c8 * 8];
        *(uint4*)(smc + r * 144 + c8 * 16) = v;
    }
    __syncthreads();

    uint32_t qf[4][4];
    #pragma unroll
    for (int kk = 0; kk < 4; kk++)
        ldsm4(qf[kk], sb + (w * 16 + (lane & 15)) * 144 + kk * 32 + (lane >> 4) * 16);
    __syncthreads();

    float o[8][4] = {};
    float m0 = -1e30f, m1 = -1e30f, l0 = 0.f, l1 = 0.f;
    const int nb = qi + 1;
    const int qrow0 = qbase + w * 16 + g;
    const int wmin  = qbase + w * 16;

    uint32_t koff[4], voff[4];
    #pragma unroll
    for (int jp = 0; jp < 4; jp++)
        koff[jp] = (jp * 16 + ((lane >> 4) << 3) + (lane & 7)) * 144
                 + ((lane >> 3) & 1) * 16;
    {
        const int qd = lane >> 3;
        #pragma unroll
        for (int jp = 0; jp < 4; jp++)
            voff[jp] = (((qd & 1) << 3) + (lane & 7)) * 144
                     + jp * 32 + ((qd >> 1) << 4);
    }

    auto loadKV = [&](int kb, int stg) {
        const int t0 = kb * AK;
        const uint32_t ks = sb + OFF_K + stg * KVBYTES;
        const uint32_t vs = sb + OFF_V + stg * KVBYTES;
        #pragma unroll
        for (int it = 0; it < 4; it++) {
            const int idx = tid + it * 128;
            const int r = idx >> 3, c8 = idx & 7;
            cp_async16(ks + r * 144 + c8 * 16,
                       &KH[rb + (size_t)(t0 + r) * E_ + c8 * 8]);
            cp_async16(vs + r * 144 + c8 * 16,
                       &VH[rb + (size_t)(t0 + r) * E_ + c8 * 8]);
        }
    };

    loadKV(0, 0); CP_COMMIT();

    for (int kb = 0; kb < nb; kb++) {
        const int stg = kb & 1;
        const int t0  = kb * AK;
        CP_WAIT0();                // load(kb) landed
        __syncthreads();           // + everyone done computing stage stg^1
        if (kb + 1 < nb) { loadKV(kb + 1, stg ^ 1); CP_COMMIT(); }

        {
            const uint32_t ks = sb + OFF_K + stg * KVBYTES;
            const uint32_t vs = sb + OFF_V + stg * KVBYTES;

            // ---- S = Q @ K^T ----
            float sc[8][4] = {};
            #pragma unroll
            for (int kk = 0; kk < 4; kk++) {
                uint32_t kf[4][4];
                #pragma unroll
                for (int jp = 0; jp < 4; jp++) ldsm4(kf[jp], ks + koff[jp] + kk * 32);
                #pragma unroll
                for (int jp = 0; jp < 4; jp++) {
                    mma_f16(sc[2 * jp],     qf[kk], &kf[jp][0]);
                    mma_f16(sc[2 * jp + 1], qf[kk], &kf[jp][2]);
                }
            }

            // ---- scale + causal mask ----
            const bool needmask = (t0 + AK - 1) >= wmin;
            #pragma unroll
            for (int jj = 0; jj < 8; jj++) {
                sc[jj][0] *= 0.125f; sc[jj][1] *= 0.125f;
                sc[jj][2] *= 0.125f; sc[jj][3] *= 0.125f;
                if (needmask) {
                    const int cg = t0 + jj * 8 + 2 * c;
                    const int r0 = qrow0, r1 = qrow0 + 8;
                    if (!((cg     < r0) || (r0 == 0 && cg == 0)))     sc[jj][0] = -1e30f;
                    if (!((cg + 1 < r0) || (r0 == 0 && cg + 1 == 0))) sc[jj][1] = -1e30f;
                    if (!(cg     < r1)) sc[jj][2] = -1e30f;
                    if (!(cg + 1 < r1)) sc[jj][3] = -1e30f;
                }
            }

            // ---- online softmax ----
            float mx0 = -1e30f, mx1 = -1e30f;
            #pragma unroll
            for (int jj = 0; jj < 8; jj++) {
                mx0 = fmaxf(mx0, fmaxf(sc[jj][0], sc[jj][1]));
                mx1 = fmaxf(mx1, fmaxf(sc[jj][2], sc[jj][3]));
            }
            mx0 = fmaxf(mx0, __shfl_xor_sync(0xffffffffu, mx0, 1));
            mx0 = fmaxf(mx0, __shfl_xor_sync(0xffffffffu, mx0, 2));
            mx1 = fmaxf(mx1, __shfl_xor_sync(0xffffffffu, mx1, 1));
            mx1 = fmaxf(mx1, __shfl_xor_sync(0xffffffffu, mx1, 2));
            const float mn0 = fmaxf(m0, mx0), mn1 = fmaxf(m1, mx1);
            const float a0 = __expf(m0 - mn0), a1 = __expf(m1 - mn1);
            float s0 = 0.f, s1 = 0.f;
            #pragma unroll
            for (int jj = 0; jj < 8; jj++) {
                sc[jj][0] = __expf(sc[jj][0] - mn0);
                sc[jj][1] = __expf(sc[jj][1] - mn0);
                sc[jj][2] = __expf(sc[jj][2] - mn1);
                sc[jj][3] = __expf(sc[jj][3] - mn1);
                s0 += sc[jj][0] + sc[jj][1];
                s1 += sc[jj][2] + sc[jj][3];
            }
            s0 += __shfl_xor_sync(0xffffffffu, s0, 1);
            s0 += __shfl_xor_sync(0xffffffffu, s0, 2);
            s1 += __shfl_xor_sync(0xffffffffu, s1, 1);
            s1 += __shfl_xor_sync(0xffffffffu, s1, 2);
            l0 = l0 * a0 + s0; l1 = l1 * a1 + s1;
            m0 = mn0; m1 = mn1;
            #pragma unroll
            for (int jj = 0; jj < 8; jj++) {
                o[jj][0] *= a0; o[jj][1] *= a0;
                o[jj][2] *= a1; o[jj][3] *= a1;
            }

            // ---- O += P @ V ----
            #pragma unroll
            for (int kk = 0; kk < 4; kk++) {
                uint32_t pf[4];
                pf[0] = h2pack(sc[2 * kk][0],     sc[2 * kk][1]);
                pf[1] = h2pack(sc[2 * kk][2],     sc[2 * kk][3]);
                pf[2] = h2pack(sc[2 * kk + 1][0], sc[2 * kk + 1][1]);
                pf[3] = h2pack(sc[2 * kk + 1][2], sc[2 * kk + 1][3]);
                uint32_t vf[4][4];
                #pragma unroll
                for (int jp = 0; jp < 4; jp++)
                    ldsm4t(vf[jp], vs + voff[jp] + kk * 16 * 144);
                #pragma unroll
                for (int jp = 0; jp < 4; jp++) {
                    mma_f16(o[2 * jp],     pf, &vf[jp][0]);
                    mma_f16(o[2 * jp + 1], pf, &vf[jp][2]);
                }
            }
        }
    }

    // ---- epilogue: normalize, convert to fp16 for Wo GEMM ----
    const float il0 = 1.f / l0, il1 = 1.f / l1;
    #pragma unroll
    for (int jj = 0; jj < 8; jj++) {
        const int col = jj * 8 + 2 * c;
        *(uint32_t*)&AH[rb + (size_t)qrow0 * E_ + col] =
            h2pack(o[jj][0] * il0, o[jj][1] * il0);
        *(uint32_t*)&AH[rb + (size_t)(qrow0 + 8) * E_ + col] =
            h2pack(o[jj][2] * il1, o[jj][3] * il1);
    }
}

// ===========================================================================
extern "C" void kernel_launch(void* const* d_in, const int* in_sizes, int n_in,
                              void* d_out, int out_size)
{
    const float* q  = (const float*)d_in[0];
    const float* k  = (const float*)d_in[1];
    const float* v  = (const float*)d_in[2];
    const float* Wq = (const float*)d_in[3];
    const float* Wk = (const float*)d_in[4];
    const float* Wv = (const float*)d_in[5];
    const float* bv = (const float*)d_in[6];
    const float* Wo = (const float*)d_in[7];
    const float* bo = (const float*)d_in[8];
    float* out = (float*)d_out;

    __half *qc, *kc, *vc, *wc, *qh, *kh, *vh, *ah;
    cudaGetSymbolAddress((void**)&qc, g_qc);
    cudaGetSymbolAddress((void**)&kc, g_kc);
    cudaGetSymbolAddress((void**)&vc, g_vc);
    cudaGetSymbolAddress((void**)&wc, g_wc);
    cudaGetSymbolAddress((void**)&qh, g_qh);
    cudaGetSymbolAddress((void**)&kh, g_kh);
    cudaGetSymbolAddress((void**)&vh, g_vh);
    cudaGetSymbolAddress((void**)&ah, g_ah);

    auto* gemm_qkv = gemm_t<128, 64, 4, 1, 3>;
    auto* gemm_wo  = gemm_t<64, 64, 2, 2, 4>;
    cudaFuncSetAttribute(gemm_qkv, cudaFuncAttributeMaxDynamicSharedMemorySize,
                         QKV_SMEM);
    cudaFuncSetAttribute(gemm_wo, cudaFuncAttributeMaxDynamicSharedMemorySize,
                         WO_SMEM);
    cudaFuncSetAttribute(attn_mma, cudaFuncAttributeMaxDynamicSharedMemorySize,
                         ATTN_SMEM);

    // ---- fp16 conversion prepass (one launch) ----
    round_h_all<<<(TOT8 + 255) / 256, 256>>>(
        (const float4*)q, (const float4*)k, (const float4*)v,
        (const float4*)Wq, (const float4*)Wk, (const float4*)Wv, (const float4*)Wo,
        qc, kc, vc, wc);

    // ---- fused Q/K/V projections: 128x64 tiles (fp16 out) ----
    const dim3 gqkv(M_ / 128, E_ / 64, 3);     // (32, 16, 3) = 1536 tiles
    gemm_qkv<<<gqkv, 128, QKV_SMEM>>>(qc, kc, vc,
                                      wc, wc + (size_t)E_ * E_, wc + 2 * (size_t)E_ * E_,
                                      nullptr,
                                      qh, kh, vh,
                                      nullptr, nullptr, bv);

    // ---- attention (AQ=64, 3 CTAs/SM) ----
    const dim3 agrd(S_ / AQ, B_ * H_);         // (32, 32)
    attn_mma<<<agrd, 128, ATTN_SMEM>>>(qh, kh, vh, ah);

    // ---- output projection: 64x64 tiles (fp32 out + bias) ----
    const dim3 gwo(M_ / 64, E_ / 64, 1);       // (64, 16) = 1024 tiles
    gemm_wo<<<gwo, 128, WO_SMEM>>>(ah, ah, ah,
                                   wc + 3 * (size_t)E_ * E_, nullptr, nullptr,
                                   out,
                                   nullptr, nullptr, nullptr,
                                   bo, bo, bo);
}

// round 15
// speedup vs baseline: 1.0292x; 1.0050x over previous
#include <cuda_runtime.h>
#include <cuda_fp16.h>
#include <cstdint>

// Problem constants
#define B_   2
#define S_   2048
#define E_   1024
#define H_   16
#define HD_  64
#define M_   (B_ * S_)   // 4096 flattened rows

// Scratch (fp16)
__device__ __half g_qc[M_ * E_];
__device__ __half g_kc[M_ * E_];
__device__ __half g_vc[M_ * E_];
__device__ __half g_wc[4 * E_ * E_];
__device__ __half g_qh[M_ * E_];
__device__ __half g_kh[M_ * E_];
__device__ __half g_vh[M_ * E_];
__device__ __half g_ah[M_ * E_];

// ===========================================================================
// Helpers
// ===========================================================================
__device__ __forceinline__ uint32_t smem_u32(const void* p) {
    uint32_t a;
    asm("{ .reg .u64 t; cvta.to.shared.u64 t, %1; cvt.u32.u64 %0, t; }"
        : "=r"(a) : "l"(p));
    return a;
}

__device__ __forceinline__ void cp_async16(uint32_t dst, const void* src) {
    asm volatile("cp.async.cg.shared.global [%0], [%1], 16;"
                 :: "r"(dst), "l"(src) : "memory");
}
#define CP_COMMIT() asm volatile("cp.async.commit_group;" ::: "memory")
#define CP_WAIT0()  asm volatile("cp.async.wait_group 0;" ::: "memory")
#define CP_WAIT1()  asm volatile("cp.async.wait_group 1;" ::: "memory")

__device__ __forceinline__ void mma_f16(float* d, const uint32_t* a, const uint32_t* b) {
    asm volatile(
        "mma.sync.aligned.m16n8k16.row.col.f32.f16.f16.f32 "
        "{%0,%1,%2,%3}, {%4,%5,%6,%7}, {%8,%9}, {%0,%1,%2,%3};"
        : "+f"(d[0]), "+f"(d[1]), "+f"(d[2]), "+f"(d[3])
        : "r"(a[0]), "r"(a[1]), "r"(a[2]), "r"(a[3]), "r"(b[0]), "r"(b[1]));
}

__device__ __forceinline__ void ldsm4(uint32_t* r, uint32_t addr) {
    asm volatile("ldmatrix.sync.aligned.m8n8.x4.shared.b16 {%0,%1,%2,%3}, [%4];"
                 : "=r"(r[0]), "=r"(r[1]), "=r"(r[2]), "=r"(r[3]) : "r"(addr));
}
__device__ __forceinline__ void ldsm4t(uint32_t* r, uint32_t addr) {
    asm volatile("ldmatrix.sync.aligned.m8n8.x4.trans.shared.b16 {%0,%1,%2,%3}, [%4];"
                 : "=r"(r[0]), "=r"(r[1]), "=r"(r[2]), "=r"(r[3]) : "r"(addr));
}

__device__ __forceinline__ uint32_t h2pack(float a, float b) {
    __half2 h = __floats2half2_rn(a, b);
    return *(uint32_t*)&h;
}

// ===========================================================================
// fp32 -> fp16 conversion prepass (one launch; groups of 8 floats)
// ===========================================================================
#define ACT8 (M_ * E_ / 8)
#define W8   (E_ * E_ / 8)
#define TOT8 (3 * ACT8 + 4 * W8)

__global__ __launch_bounds__(256) void round_h_all(
    const float4* __restrict__ q, const float4* __restrict__ k,
    const float4* __restrict__ v,
    const float4* __restrict__ Wq, const float4* __restrict__ Wk,
    const float4* __restrict__ Wv, const float4* __restrict__ Wo,
    __half* __restrict__ qc, __half* __restrict__ kc,
    __half* __restrict__ vc, __half* __restrict__ wc)
{
    const long i = (long)blockIdx.x * 256 + threadIdx.x;
    if (i >= TOT8) return;
    const float4* s; __half* d; long off;
    if (i < ACT8)            { s = q; d = qc; off = i; }
    else if (i < 2L * ACT8)  { s = k; d = kc; off = i - ACT8; }
    else if (i < 3L * ACT8)  { s = v; d = vc; off = i - 2L * ACT8; }
    else {
        const long j = i - 3L * ACT8;
        s = (j < W8) ? Wq : (j < 2 * W8) ? Wk : (j < 3 * W8) ? Wv : Wo;
        d = wc + (j / W8) * (E_ * (long)E_);
        off = j % W8;
    }
    float4 u = s[2 * off], w = s[2 * off + 1];
    uint4 o;
    o.x = h2pack(u.x, u.y); o.y = h2pack(u.z, u.w);
    o.z = h2pack(w.x, w.y); o.w = h2pack(w.z, w.w);
    *(uint4*)(d + off * 8) = o;
}

// ===========================================================================
// Templated fp16 mma GEMM: C[M,1024] = A[M,1024] @ W[1024,1024]^T (+ bias)
// TMt x TNt CTA tile, 4 warps (MW x NW), K-chunk 64 halves, ldmatrix.x4,
// fp32 accumulate. NSTG=2: single-sync double buffer (big tiles).
// NSTG=3: 3-stage ring with wait_group 1 (small tiles, deeper prefetch).
// ===========================================================================
#define GTK   64
#define NCH   (E_ / GTK)                  // 16
#define ROWB  144                          // 64 halves + 16B pad

template<int TMt, int TNt, int MW, int NW, int MINB, int NSTG>
__global__ __launch_bounds__(128, MINB) void gemm_t(
    const __half* __restrict__ A0, const __half* __restrict__ A1,
    const __half* __restrict__ A2,
    const __half* __restrict__ W0, const __half* __restrict__ W1,
    const __half* __restrict__ W2,
    float* __restrict__ Cf,
    __half* __restrict__ Ch0, __half* __restrict__ Ch1, __half* __restrict__ Ch2,
    const float* __restrict__ b0, const float* __restrict__ b1,
    const float* __restrict__ b2)
{
    constexpr int MI  = TMt / MW / 16;     // m16 frags per warp
    constexpr int JP  = TNt / NW / 16;     // n16 ldsm groups per warp
    constexpr int STG = (TMt + TNt) * ROWB;

    extern __shared__ char smem[];
    const int tid  = threadIdx.x;
    const int lane = tid & 31;
    const int wid  = tid >> 5;
    const int wm   = wid % MW;
    const int wn   = wid / MW;

    const int z = blockIdx.z;
    const __half* A = (z == 0) ? A0 : (z == 1) ? A1 : A2;
    const __half* W = (z == 0) ? W0 : (z == 1) ? W1 : W2;
    __half* Ch = (z == 0) ? Ch0 : (z == 1) ? Ch1 : Ch2;
    const float* bias = (z == 0) ? b0 : (z == 1) ? b1 : b2;

    const int m0 = blockIdx.x * TMt;
    const int n0 = blockIdx.y * TNt;
    const uint32_t sb = smem_u32(smem);

    uint32_t aoff[MI], boff[JP];
    #pragma unroll
    for (int ii = 0; ii < MI; ii++)
        aoff[ii] = (wm * (TMt / MW) + ii * 16 + (lane & 15)) * ROWB
                 + (lane >> 4) * 16;
    #pragma unroll
    for (int jp = 0; jp < JP; jp++)
        boff[jp] = TMt * ROWB
                 + (wn * (TNt / NW) + jp * 16 + ((lane >> 4) << 3) + (lane & 7)) * ROWB
                 + ((lane >> 3) & 1) * 16;

    float acc[MI][2 * JP][4] = {};

    auto load_chunk = [&](int ch, int stg) {
        const int k0 = ch * GTK;
        const uint32_t as = sb + stg * STG;
        const uint32_t bs = as + TMt * ROWB;
        #pragma unroll
        for (int it = 0; it < TMt / 16; it++) {
            const int idx = tid + it * 128;
            const int r = idx >> 3, c8 = idx & 7;
            cp_async16(as + r * ROWB + c8 * 16,
                       A + (size_t)(m0 + r) * E_ + k0 + c8 * 8);
        }
        #pragma unroll
        for (int it = 0; it < TNt / 16; it++) {
            const int idx = tid + it * 128;
            const int r = idx >> 3, c8 = idx & 7;
            cp_async16(bs + r * ROWB + c8 * 16,
                       W + (size_t)(n0 + r) * E_ + k0 + c8 * 8);
        }
    };

    auto compute_stage = [&](int stg) {
        const uint32_t su = sb + stg * STG;
        #pragma unroll
        for (int kk = 0; kk < 4; kk++) {
            const uint32_t kb = su + kk * 32;
            uint32_t af[MI][4], bf[JP][4];
            #pragma unroll
            for (int ii = 0; ii < MI; ii++) ldsm4(af[ii], kb + aoff[ii]);
            #pragma unroll
            for (int jp = 0; jp < JP; jp++) ldsm4(bf[jp], kb + boff[jp]);
            #pragma unroll
            for (int ii = 0; ii < MI; ii++)
                #pragma unroll
                for (int jp = 0; jp < JP; jp++) {
                    mma_f16(acc[ii][2 * jp],     af[ii], &bf[jp][0]);
                    mma_f16(acc[ii][2 * jp + 1], af[ii], &bf[jp][2]);
                }
        }
    };

    if (NSTG == 2) {
        load_chunk(0, 0); CP_COMMIT();
        for (int i = 0; i < NCH; i++) {
            CP_WAIT0();            // load(i) landed (only outstanding group)
            __syncthreads();       // + everyone done computing stage (i+1)&1
            if (i + 1 < NCH) { load_chunk(i + 1, (i + 1) & 1); CP_COMMIT(); }
            compute_stage(i & 1);
        }
    } else {
        load_chunk(0, 0); CP_COMMIT();
        load_chunk(1, 1); CP_COMMIT();
        for (int i = 0; i < NCH; i++) {
            CP_WAIT1();            // load(i) landed (older of <=2 groups)
            __syncthreads();       // + everyone done computing stage (i) % 3 reuse
            if (i + 2 < NCH) { load_chunk(i + 2, (i + 2) % 3); CP_COMMIT(); }
            else CP_COMMIT();      // keep group accounting exact
            compute_stage(i % 3);
        }
    }

    const int g = lane >> 2;
    const int c = lane & 3;
    #pragma unroll
    for (int ii = 0; ii < MI; ii++) {
        const int r0 = m0 + wm * (TMt / MW) + ii * 16 + g;
        #pragma unroll
        for (int jj = 0; jj < 2 * JP; jj++) {
            const int cc = n0 + wn * (TNt / NW) + jj * 8 + 2 * c;
            float bx = 0.f, by = 0.f;
            if (bias) { bx = bias[cc]; by = bias[cc + 1]; }
            const float v00 = acc[ii][jj][0] + bx, v01 = acc[ii][jj][1] + by;
            const float v10 = acc[ii][jj][2] + bx, v11 = acc[ii][jj][3] + by;
            if (Ch) {
                *(uint32_t*)&Ch[(size_t)r0 * E_ + cc]       = h2pack(v00, v01);
                *(uint32_t*)&Ch[(size_t)(r0 + 8) * E_ + cc] = h2pack(v10, v11);
            } else {
                *(float2*)&Cf[(size_t)r0 * E_ + cc]       = make_float2(v00, v01);
                *(float2*)&Cf[(size_t)(r0 + 8) * E_ + cc] = make_float2(v10, v11);
            }
        }
    }
}

// QKV: 128x64 tiles, warps 4x1 (32x64), 2-stage, 3 CTAs/SM, smem 55296
// Wo:  64x64 tiles,  warps 2x2 (32x32), 3-stage, 4 CTAs/SM, smem 55296
#define QKV_SMEM (2 * (128 + 64) * ROWB)
#define WO_SMEM  (3 * (64 + 64) * ROWB)

// ===========================================================================
// fp16 tensor-core flash attention, strict-causal with (0,0) exception.
// CTA = (b,h) x 64 q-rows; 4 warps x 16 rows; K/V blocks of 64; 3 CTAs/SM.
// Single-sync pipeline (R14).
// ===========================================================================
#define AQ    64
#define AK    64
#define QBYTES (AQ * 144)
#define KVBYTES (AK * 144)
#define OFF_K  QBYTES
#define OFF_V  (OFF_K + 2 * KVBYTES)
#define ATTN_SMEM (OFF_V + 2 * KVBYTES)       // 46080

__global__ __launch_bounds__(128, 3) void attn_mma(
    const __half* __restrict__ QH, const __half* __restrict__ KH,
    const __half* __restrict__ VH, __half* __restrict__ AH)
{
    extern __shared__ char smc[];
    const int tid  = threadIdx.x;
    const int lane = tid & 31;
    const int w    = tid >> 5;
    const int g    = lane >> 2;
    const int c    = lane & 3;
    const int qi   = (int)(gridDim.x - 1) - (int)blockIdx.x;  // heavy tiles first
    const int bh   = blockIdx.y;
    const int b    = bh >> 4;
    const int h    = bh & 15;
    const int qbase = qi * AQ;
    const size_t rb = (size_t)b * S_ * E_ + (size_t)h * HD_;

    const uint32_t sb = smem_u32(smc);

    // ---- load Q tile (64 x 64 halves) ----
    #pragma unroll
    for (int it = 0; it < 4; it++) {
        const int idx = tid + it * 128;
        const int r = idx >> 3, c8 = idx & 7;
        uint4 v = *(const uint4*)&QH[rb + (size_t)(qbase + r) * E_ + c8 * 8];
        *(uint4*)(smc + r * 144 + c8 * 16) = v;
    }
    __syncthreads();

    uint32_t qf[4][4];
    #pragma unroll
    for (int kk = 0; kk < 4; kk++)
        ldsm4(qf[kk], sb + (w * 16 + (lane & 15)) * 144 + kk * 32 + (lane >> 4) * 16);
    __syncthreads();

    float o[8][4] = {};
    float m0 = -1e30f, m1 = -1e30f, l0 = 0.f, l1 = 0.f;
    const int nb = qi + 1;
    const int qrow0 = qbase + w * 16 + g;
    const int wmin  = qbase + w * 16;

    uint32_t koff[4], voff[4];
    #pragma unroll
    for (int jp = 0; jp < 4; jp++)
        koff[jp] = (jp * 16 + ((lane >> 4) << 3) + (lane & 7)) * 144
                 + ((lane >> 3) & 1) * 16;
    {
        const int qd = lane >> 3;
        #pragma unroll
        for (int jp = 0; jp < 4; jp++)
            voff[jp] = (((qd & 1) << 3) + (lane & 7)) * 144
                     + jp * 32 + ((qd >> 1) << 4);
    }

    auto loadKV = [&](int kb, int stg) {
        const int t0 = kb * AK;
        const uint32_t ks = sb + OFF_K + stg * KVBYTES;
        const uint32_t vs = sb + OFF_V + stg * KVBYTES;
        #pragma unroll
        for (int it = 0; it < 4; it++) {
            const int idx = tid + it * 128;
            const int r = idx >> 3, c8 = idx & 7;
            cp_async16(ks + r * 144 + c8 * 16,
                       &KH[rb + (size_t)(t0 + r) * E_ + c8 * 8]);
            cp_async16(vs + r * 144 + c8 * 16,
                       &VH[rb + (size_t)(t0 + r) * E_ + c8 * 8]);
        }
    };

    loadKV(0, 0); CP_COMMIT();

    for (int kb = 0; kb < nb; kb++) {
        const int stg = kb & 1;
        const int t0  = kb * AK;
        CP_WAIT0();                // load(kb) landed
        __syncthreads();           // + everyone done computing stage stg^1
        if (kb + 1 < nb) { loadKV(kb + 1, stg ^ 1); CP_COMMIT(); }

        {
            const uint32_t ks = sb + OFF_K + stg * KVBYTES;
            const uint32_t vs = sb + OFF_V + stg * KVBYTES;

            // ---- S = Q @ K^T ----
            float sc[8][4] = {};
            #pragma unroll
            for (int kk = 0; kk < 4; kk++) {
                uint32_t kf[4][4];
                #pragma unroll
                for (int jp = 0; jp < 4; jp++) ldsm4(kf[jp], ks + koff[jp] + kk * 32);
                #pragma unroll
                for (int jp = 0; jp < 4; jp++) {
                    mma_f16(sc[2 * jp],     qf[kk], &kf[jp][0]);
                    mma_f16(sc[2 * jp + 1], qf[kk], &kf[jp][2]);
                }
            }

            // ---- scale + causal mask ----
            const bool needmask = (t0 + AK - 1) >= wmin;
            #pragma unroll
            for (int jj = 0; jj < 8; jj++) {
                sc[jj][0] *= 0.125f; sc[jj][1] *= 0.125f;
                sc[jj][2] *= 0.125f; sc[jj][3] *= 0.125f;
                if (needmask) {
                    const int cg = t0 + jj * 8 + 2 * c;
                    const int r0 = qrow0, r1 = qrow0 + 8;
                    if (!((cg     < r0) || (r0 == 0 && cg == 0)))     sc[jj][0] = -1e30f;
                    if (!((cg + 1 < r0) || (r0 == 0 && cg + 1 == 0))) sc[jj][1] = -1e30f;
                    if (!(cg     < r1)) sc[jj][2] = -1e30f;
                    if (!(cg + 1 < r1)) sc[jj][3] = -1e30f;
                }
            }

            // ---- online softmax ----
            float mx0 = -1e30f, mx1 = -1e30f;
            #pragma unroll
            for (int jj = 0; jj < 8; jj++) {
                mx0 = fmaxf(mx0, fmaxf(sc[jj][0], sc[jj][1]));
                mx1 = fmaxf(mx1, fmaxf(sc[jj][2], sc[jj][3]));
            }
            mx0 = fmaxf(mx0, __shfl_xor_sync(0xffffffffu, mx0, 1));
            mx0 = fmaxf(mx0, __shfl_xor_sync(0xffffffffu, mx0, 2));
            mx1 = fmaxf(mx1, __shfl_xor_sync(0xffffffffu, mx1, 1));
            mx1 = fmaxf(mx1, __shfl_xor_sync(0xffffffffu, mx1, 2));
            const float mn0 = fmaxf(m0, mx0), mn1 = fmaxf(m1, mx1);
            const float a0 = __expf(m0 - mn0), a1 = __expf(m1 - mn1);
            float s0 = 0.f, s1 = 0.f;
            #pragma unroll
            for (int jj = 0; jj < 8; jj++) {
                sc[jj][0] = __expf(sc[jj][0] - mn0);
                sc[jj][1] = __expf(sc[jj][1] - mn0);
                sc[jj][2] = __expf(sc[jj][2] - mn1);
                sc[jj][3] = __expf(sc[jj][3] - mn1);
                s0 += sc[jj][0] + sc[jj][1];
                s1 += sc[jj][2] + sc[jj][3];
            }
            s0 += __shfl_xor_sync(0xffffffffu, s0, 1);
            s0 += __shfl_xor_sync(0xffffffffu, s0, 2);
            s1 += __shfl_xor_sync(0xffffffffu, s1, 1);
            s1 += __shfl_xor_sync(0xffffffffu, s1, 2);
            l0 = l0 * a0 + s0; l1 = l1 * a1 + s1;
            m0 = mn0; m1 = mn1;
            #pragma unroll
            for (int jj = 0; jj < 8; jj++) {
                o[jj][0] *= a0; o[jj][1] *= a0;
                o[jj][2] *= a1; o[jj][3] *= a1;
            }

            // ---- O += P @ V ----
            #pragma unroll
            for (int kk = 0; kk < 4; kk++) {
                uint32_t pf[4];
                pf[0] = h2pack(sc[2 * kk][0],     sc[2 * kk][1]);
                pf[1] = h2pack(sc[2 * kk][2],     sc[2 * kk][3]);
                pf[2] = h2pack(sc[2 * kk + 1][0], sc[2 * kk + 1][1]);
                pf[3] = h2pack(sc[2 * kk + 1][2], sc[2 * kk + 1][3]);
                uint32_t vf[4][4];
                #pragma unroll
                for (int jp = 0; jp < 4; jp++)
                    ldsm4t(vf[jp], vs + voff[jp] + kk * 16 * 144);
                #pragma unroll
                for (int jp = 0; jp < 4; jp++) {
                    mma_f16(o[2 * jp],     pf, &vf[jp][0]);
                    mma_f16(o[2 * jp + 1], pf, &vf[jp][2]);
                }
            }
        }
    }

    // ---- epilogue: normalize, convert to fp16 for Wo GEMM ----
    const float il0 = 1.f / l0, il1 = 1.f / l1;
    #pragma unroll
    for (int jj = 0; jj < 8; jj++) {
        const int col = jj * 8 + 2 * c;
        *(uint32_t*)&AH[rb + (size_t)qrow0 * E_ + col] =
            h2pack(o[jj][0] * il0, o[jj][1] * il0);
        *(uint32_t*)&AH[rb + (size_t)(qrow0 + 8) * E_ + col] =
            h2pack(o[jj][2] * il1, o[jj][3] * il1);
    }
}

// ===========================================================================
extern "C" void kernel_launch(void* const* d_in, const int* in_sizes, int n_in,
                              void* d_out, int out_size)
{
    const float* q  = (const float*)d_in[0];
    const float* k  = (const float*)d_in[1];
    const float* v  = (const float*)d_in[2];
    const float* Wq = (const float*)d_in[3];
    const float* Wk = (const float*)d_in[4];
    const float* Wv = (const float*)d_in[5];
    const float* bv = (const float*)d_in[6];
    const float* Wo = (const float*)d_in[7];
    const float* bo = (const float*)d_in[8];
    float* out = (float*)d_out;

    __half *qc, *kc, *vc, *wc, *qh, *kh, *vh, *ah;
    cudaGetSymbolAddress((void**)&qc, g_qc);
    cudaGetSymbolAddress((void**)&kc, g_kc);
    cudaGetSymbolAddress((void**)&vc, g_vc);
    cudaGetSymbolAddress((void**)&wc, g_wc);
    cudaGetSymbolAddress((void**)&qh, g_qh);
    cudaGetSymbolAddress((void**)&kh, g_kh);
    cudaGetSymbolAddress((void**)&vh, g_vh);
    cudaGetSymbolAddress((void**)&ah, g_ah);

    auto* gemm_qkv = gemm_t<128, 64, 4, 1, 3, 2>;   // 2-stage single-sync
    auto* gemm_wo  = gemm_t<64, 64, 2, 2, 4, 3>;    // 3-stage wait1
    cudaFuncSetAttribute(gemm_qkv, cudaFuncAttributeMaxDynamicSharedMemorySize,
                         QKV_SMEM);
    cudaFuncSetAttribute(gemm_wo, cudaFuncAttributeMaxDynamicSharedMemorySize,
                         WO_SMEM);
    cudaFuncSetAttribute(attn_mma, cudaFuncAttributeMaxDynamicSharedMemorySize,
                         ATTN_SMEM);

    // ---- fp16 conversion prepass (one launch) ----
    round_h_all<<<(TOT8 + 255) / 256, 256>>>(
        (const float4*)q, (const float4*)k, (const float4*)v,
        (const float4*)Wq, (const float4*)Wk, (const float4*)Wv, (const float4*)Wo,
        qc, kc, vc, wc);

    // ---- fused Q/K/V projections: 128x64 tiles (fp16 out) ----
    const dim3 gqkv(M_ / 128, E_ / 64, 3);     // (32, 16, 3) = 1536 tiles
    gemm_qkv<<<gqkv, 128, QKV_SMEM>>>(qc, kc, vc,
                                      wc, wc + (size_t)E_ * E_, wc + 2 * (size_t)E_ * E_,
                                      nullptr,
                                      qh, kh, vh,
                                      nullptr, nullptr, bv);

    // ---- attention (AQ=64, 3 CTAs/SM) ----
    const dim3 agrd(S_ / AQ, B_ * H_);         // (32, 32)
    attn_mma<<<agrd, 128, ATTN_SMEM>>>(qh, kh, vh, ah);

    // ---- output projection: 64x64 tiles, 3-stage (fp32 out + bias) ----
    const dim3 gwo(M_ / 64, E_ / 64, 1);       // (64, 16) = 1024 tiles
    gemm_wo<<<gwo, 128, WO_SMEM>>>(ah, ah, ah,
                                   wc + 3 * (size_t)E_ * E_, nullptr, nullptr,
                                   out,
                                   nullptr, nullptr, nullptr,
                                   bo, bo, bo);
}

// round 16
// speedup vs baseline: 1.0297x; 1.0004x over previous
#include <cuda_runtime.h>
#include <cuda_fp16.h>
#include <cstdint>

// Problem constants
#define B_   2
#define S_   2048
#define E_   1024
#define H_   16
#define HD_  64
#define M_   (B_ * S_)   // 4096 flattened rows

// Scratch (fp16)
__device__ __half g_qc[M_ * E_];
__device__ __half g_kc[M_ * E_];
__device__ __half g_vc[M_ * E_];
__device__ __half g_wc[4 * E_ * E_];
__device__ __half g_qh[M_ * E_];
__device__ __half g_kh[M_ * E_];
__device__ __half g_vh[M_ * E_];
__device__ __half g_ah[M_ * E_];

// ===========================================================================
// Helpers
// ===========================================================================
__device__ __forceinline__ uint32_t smem_u32(const void* p) {
    uint32_t a;
    asm("{ .reg .u64 t; cvta.to.shared.u64 t, %1; cvt.u32.u64 %0, t; }"
        : "=r"(a) : "l"(p));
    return a;
}

__device__ __forceinline__ void cp_async16(uint32_t dst, const void* src) {
    asm volatile("cp.async.cg.shared.global [%0], [%1], 16;"
                 :: "r"(dst), "l"(src) : "memory");
}
#define CP_COMMIT() asm volatile("cp.async.commit_group;" ::: "memory")
#define CP_WAIT0()  asm volatile("cp.async.wait_group 0;" ::: "memory")
#define CP_WAIT1()  asm volatile("cp.async.wait_group 1;" ::: "memory")

__device__ __forceinline__ void mma_f16(float* d, const uint32_t* a, const uint32_t* b) {
    asm volatile(
        "mma.sync.aligned.m16n8k16.row.col.f32.f16.f16.f32 "
        "{%0,%1,%2,%3}, {%4,%5,%6,%7}, {%8,%9}, {%0,%1,%2,%3};"
        : "+f"(d[0]), "+f"(d[1]), "+f"(d[2]), "+f"(d[3])
        : "r"(a[0]), "r"(a[1]), "r"(a[2]), "r"(a[3]), "r"(b[0]), "r"(b[1]));
}

__device__ __forceinline__ void ldsm4(uint32_t* r, uint32_t addr) {
    asm volatile("ldmatrix.sync.aligned.m8n8.x4.shared.b16 {%0,%1,%2,%3}, [%4];"
                 : "=r"(r[0]), "=r"(r[1]), "=r"(r[2]), "=r"(r[3]) : "r"(addr));
}
__device__ __forceinline__ void ldsm4t(uint32_t* r, uint32_t addr) {
    asm volatile("ldmatrix.sync.aligned.m8n8.x4.trans.shared.b16 {%0,%1,%2,%3}, [%4];"
                 : "=r"(r[0]), "=r"(r[1]), "=r"(r[2]), "=r"(r[3]) : "r"(addr));
}

__device__ __forceinline__ uint32_t h2pack(float a, float b) {
    __half2 h = __floats2half2_rn(a, b);
    return *(uint32_t*)&h;
}

// ===========================================================================
// fp32 -> fp16 conversion prepass (one launch; groups of 8 floats)
// ===========================================================================
#define ACT8 (M_ * E_ / 8)
#define W8   (E_ * E_ / 8)
#define TOT8 (3 * ACT8 + 4 * W8)

__global__ __launch_bounds__(256) void round_h_all(
    const float4* __restrict__ q, const float4* __restrict__ k,
    const float4* __restrict__ v,
    const float4* __restrict__ Wq, const float4* __restrict__ Wk,
    const float4* __restrict__ Wv, const float4* __restrict__ Wo,
    __half* __restrict__ qc, __half* __restrict__ kc,
    __half* __restrict__ vc, __half* __restrict__ wc)
{
    const long i = (long)blockIdx.x * 256 + threadIdx.x;
    if (i >= TOT8) return;
    const float4* s; __half* d; long off;
    if (i < ACT8)            { s = q; d = qc; off = i; }
    else if (i < 2L * ACT8)  { s = k; d = kc; off = i - ACT8; }
    else if (i < 3L * ACT8)  { s = v; d = vc; off = i - 2L * ACT8; }
    else {
        const long j = i - 3L * ACT8;
        s = (j < W8) ? Wq : (j < 2 * W8) ? Wk : (j < 3 * W8) ? Wv : Wo;
        d = wc + (j / W8) * (E_ * (long)E_);
        off = j % W8;
    }
    float4 u = s[2 * off], w = s[2 * off + 1];
    uint4 o;
    o.x = h2pack(u.x, u.y); o.y = h2pack(u.z, u.w);
    o.z = h2pack(w.x, w.y); o.w = h2pack(w.z, w.w);
    *(uint4*)(d + off * 8) = o;
}

// ===========================================================================
// Templated fp16 mma GEMM: C[M,1024] = A[M,1024] @ W[1024,1024]^T (+ bias)
// TMt x TNt CTA tile, 4 warps (MW x NW), K-chunk 64 halves, ldmatrix.x4,
// fp32 accumulate. NSTG=2: single-sync double buffer (big tiles).
// NSTG=3: 3-stage ring with wait_group 1 (small tiles, deeper prefetch).
// ===========================================================================
#define GTK   64
#define NCH   (E_ / GTK)                  // 16
#define ROWB  144                          // 64 halves + 16B pad

template<int TMt, int TNt, int MW, int NW, int MINB, int NSTG>
__global__ __launch_bounds__(128, MINB) void gemm_t(
    const __half* __restrict__ A0, const __half* __restrict__ A1,
    const __half* __restrict__ A2,
    const __half* __restrict__ W0, const __half* __restrict__ W1,
    const __half* __restrict__ W2,
    float* __restrict__ Cf,
    __half* __restrict__ Ch0, __half* __restrict__ Ch1, __half* __restrict__ Ch2,
    const float* __restrict__ b0, const float* __restrict__ b1,
    const float* __restrict__ b2)
{
    constexpr int MI  = TMt / MW / 16;     // m16 frags per warp
    constexpr int JP  = TNt / NW / 16;     // n16 ldsm groups per warp
    constexpr int STG = (TMt + TNt) * ROWB;

    extern __shared__ char smem[];
    const int tid  = threadIdx.x;
    const int lane = tid & 31;
    const int wid  = tid >> 5;
    const int wm   = wid % MW;
    const int wn   = wid / MW;

    const int z = blockIdx.z;
    const __half* A = (z == 0) ? A0 : (z == 1) ? A1 : A2;
    const __half* W = (z == 0) ? W0 : (z == 1) ? W1 : W2;
    __half* Ch = (z == 0) ? Ch0 : (z == 1) ? Ch1 : Ch2;
    const float* bias = (z == 0) ? b0 : (z == 1) ? b1 : b2;

    const int m0 = blockIdx.x * TMt;
    const int n0 = blockIdx.y * TNt;
    const uint32_t sb = smem_u32(smem);

    uint32_t aoff[MI], boff[JP];
    #pragma unroll
    for (int ii = 0; ii < MI; ii++)
        aoff[ii] = (wm * (TMt / MW) + ii * 16 + (lane & 15)) * ROWB
                 + (lane >> 4) * 16;
    #pragma unroll
    for (int jp = 0; jp < JP; jp++)
        boff[jp] = TMt * ROWB
                 + (wn * (TNt / NW) + jp * 16 + ((lane >> 4) << 3) + (lane & 7)) * ROWB
                 + ((lane >> 3) & 1) * 16;

    float acc[MI][2 * JP][4] = {};

    auto load_chunk = [&](int ch, int stg) {
        const int k0 = ch * GTK;
        const uint32_t as = sb + stg * STG;
        const uint32_t bs = as + TMt * ROWB;
        #pragma unroll
        for (int it = 0; it < TMt / 16; it++) {
            const int idx = tid + it * 128;
            const int r = idx >> 3, c8 = idx & 7;
            cp_async16(as + r * ROWB + c8 * 16,
                       A + (size_t)(m0 + r) * E_ + k0 + c8 * 8);
        }
        #pragma unroll
        for (int it = 0; it < TNt / 16; it++) {
            const int idx = tid + it * 128;
            const int r = idx >> 3, c8 = idx & 7;
            cp_async16(bs + r * ROWB + c8 * 16,
                       W + (size_t)(n0 + r) * E_ + k0 + c8 * 8);
        }
    };

    auto compute_stage = [&](int stg) {
        const uint32_t su = sb + stg * STG;
        #pragma unroll
        for (int kk = 0; kk < 4; kk++) {
            const uint32_t kb = su + kk * 32;
            uint32_t af[MI][4], bf[JP][4];
            #pragma unroll
            for (int ii = 0; ii < MI; ii++) ldsm4(af[ii], kb + aoff[ii]);
            #pragma unroll
            for (int jp = 0; jp < JP; jp++) ldsm4(bf[jp], kb + boff[jp]);
            #pragma unroll
            for (int ii = 0; ii < MI; ii++)
                #pragma unroll
                for (int jp = 0; jp < JP; jp++) {
                    mma_f16(acc[ii][2 * jp],     af[ii], &bf[jp][0]);
                    mma_f16(acc[ii][2 * jp + 1], af[ii], &bf[jp][2]);
                }
        }
    };

    if (NSTG == 2) {
        load_chunk(0, 0); CP_COMMIT();
        for (int i = 0; i < NCH; i++) {
            CP_WAIT0();            // load(i) landed (only outstanding group)
            __syncthreads();       // + everyone done computing stage (i+1)&1
            if (i + 1 < NCH) { load_chunk(i + 1, (i + 1) & 1); CP_COMMIT(); }
            compute_stage(i & 1);
        }
    } else {
        load_chunk(0, 0); CP_COMMIT();
        load_chunk(1, 1); CP_COMMIT();
        for (int i = 0; i < NCH; i++) {
            CP_WAIT1();            // load(i) landed (older of <=2 groups)
            __syncthreads();       // + everyone done computing stage (i) % 3 reuse
            if (i + 2 < NCH) { load_chunk(i + 2, (i + 2) % 3); CP_COMMIT(); }
            else CP_COMMIT();      // keep group accounting exact
            compute_stage(i % 3);
        }
    }

    const int g = lane >> 2;
    const int c = lane & 3;
    #pragma unroll
    for (int ii = 0; ii < MI; ii++) {
        const int r0 = m0 + wm * (TMt / MW) + ii * 16 + g;
        #pragma unroll
        for (int jj = 0; jj < 2 * JP; jj++) {
            const int cc = n0 + wn * (TNt / NW) + jj * 8 + 2 * c;
            float bx = 0.f, by = 0.f;
            if (bias) { bx = bias[cc]; by = bias[cc + 1]; }
            const float v00 = acc[ii][jj][0] + bx, v01 = acc[ii][jj][1] + by;
            const float v10 = acc[ii][jj][2] + bx, v11 = acc[ii][jj][3] + by;
            if (Ch) {
                *(uint32_t*)&Ch[(size_t)r0 * E_ + cc]       = h2pack(v00, v01);
                *(uint32_t*)&Ch[(size_t)(r0 + 8) * E_ + cc] = h2pack(v10, v11);
            } else {
                *(float2*)&Cf[(size_t)r0 * E_ + cc]       = make_float2(v00, v01);
                *(float2*)&Cf[(size_t)(r0 + 8) * E_ + cc] = make_float2(v10, v11);
            }
        }
    }
}

// QKV: 128x64 tiles, warps 4x1 (32x64), 2-stage, 3 CTAs/SM, smem 55296
// Wo:  64x64 tiles,  warps 2x2 (32x32), 3-stage, 4 CTAs/SM, smem 55296
#define QKV_SMEM (2 * (128 + 64) * ROWB)
#define WO_SMEM  (3 * (64 + 64) * ROWB)

// ===========================================================================
// fp16 tensor-core flash attention, strict-causal with (0,0) exception.
// CTA = (b,h) x 64 q-rows; 4 warps x 16 rows; K/V blocks of 64; 4 CTAs/SM.
// Single-sync pipeline.
// ===========================================================================
#define AQ    64
#define AK    64
#define QBYTES (AQ * 144)
#define KVBYTES (AK * 144)
#define OFF_K  QBYTES
#define OFF_V  (OFF_K + 2 * KVBYTES)
#define ATTN_SMEM (OFF_V + 2 * KVBYTES)       // 46080

__global__ __launch_bounds__(128, 4) void attn_mma(
    const __half* __restrict__ QH, const __half* __restrict__ KH,
    const __half* __restrict__ VH, __half* __restrict__ AH)
{
    extern __shared__ char smc[];
    const int tid  = threadIdx.x;
    const int lane = tid & 31;
    const int w    = tid >> 5;
    const int g    = lane >> 2;
    const int c    = lane & 3;
    const int qi   = (int)(gridDim.x - 1) - (int)blockIdx.x;  // heavy tiles first
    const int bh   = blockIdx.y;
    const int b    = bh >> 4;
    const int h    = bh & 15;
    const int qbase = qi * AQ;
    const size_t rb = (size_t)b * S_ * E_ + (size_t)h * HD_;

    const uint32_t sb = smem_u32(smc);

    // ---- load Q tile (64 x 64 halves) ----
    #pragma unroll
    for (int it = 0; it < 4; it++) {
        const int idx = tid + it * 128;
        const int r = idx >> 3, c8 = idx & 7;
        uint4 v = *(const uint4*)&QH[rb + (size_t)(qbase + r) * E_ + c8 * 8];
        *(uint4*)(smc + r * 144 + c8 * 16) = v;
    }
    __syncthreads();

    uint32_t qf[4][4];
    #pragma unroll
    for (int kk = 0; kk < 4; kk++)
        ldsm4(qf[kk], sb + (w * 16 + (lane & 15)) * 144 + kk * 32 + (lane >> 4) * 16);
    __syncthreads();

    float o[8][4] = {};
    float m0 = -1e30f, m1 = -1e30f, l0 = 0.f, l1 = 0.f;
    const int nb = qi + 1;
    const int qrow0 = qbase + w * 16 + g;
    const int wmin  = qbase + w * 16;

    uint32_t koff[4], voff[4];
    #pragma unroll
    for (int jp = 0; jp < 4; jp++)
        koff[jp] = (jp * 16 + ((lane >> 4) << 3) + (lane & 7)) * 144
                 + ((lane >> 3) & 1) * 16;
    {
        const int qd = lane >> 3;
        #pragma unroll
        for (int jp = 0; jp < 4; jp++)
            voff[jp] = (((qd & 1) << 3) + (lane & 7)) * 144
                     + jp * 32 + ((qd >> 1) << 4);
    }

    auto loadKV = [&](int kb, int stg) {
        const int t0 = kb * AK;
        const uint32_t ks = sb + OFF_K + stg * KVBYTES;
        const uint32_t vs = sb + OFF_V + stg * KVBYTES;
        #pragma unroll
        for (int it = 0; it < 4; it++) {
            const int idx = tid + it * 128;
            const int r = idx >> 3, c8 = idx & 7;
            cp_async16(ks + r * 144 + c8 * 16,
                       &KH[rb + (size_t)(t0 + r) * E_ + c8 * 8]);
            cp_async16(vs + r * 144 + c8 * 16,
                       &VH[rb + (size_t)(t0 + r) * E_ + c8 * 8]);
        }
    };

    loadKV(0, 0); CP_COMMIT();

    for (int kb = 0; kb < nb; kb++) {
        const int stg = kb & 1;
        const int t0  = kb * AK;
        CP_WAIT0();                // load(kb) landed
        __syncthreads();           // + everyone done computing stage stg^1
        if (kb + 1 < nb) { loadKV(kb + 1, stg ^ 1); CP_COMMIT(); }

        {
            const uint32_t ks = sb + OFF_K + stg * KVBYTES;
            const uint32_t vs = sb + OFF_V + stg * KVBYTES;

            // ---- S = Q @ K^T ----
            float sc[8][4] = {};
            #pragma unroll
            for (int kk = 0; kk < 4; kk++) {
                uint32_t kf[4][4];
                #pragma unroll
                for (int jp = 0; jp < 4; jp++) ldsm4(kf[jp], ks + koff[jp] + kk * 32);
                #pragma unroll
                for (int jp = 0; jp < 4; jp++) {
                    mma_f16(sc[2 * jp],     qf[kk], &kf[jp][0]);
                    mma_f16(sc[2 * jp + 1], qf[kk], &kf[jp][2]);
                }
            }

            // ---- scale + causal mask ----
            const bool needmask = (t0 + AK - 1) >= wmin;
            #pragma unroll
            for (int jj = 0; jj < 8; jj++) {
                sc[jj][0] *= 0.125f; sc[jj][1] *= 0.125f;
                sc[jj][2] *= 0.125f; sc[jj][3] *= 0.125f;
                if (needmask) {
                    const int cg = t0 + jj * 8 + 2 * c;
                    const int r0 = qrow0, r1 = qrow0 + 8;
                    if (!((cg     < r0) || (r0 == 0 && cg == 0)))     sc[jj][0] = -1e30f;
                    if (!((cg + 1 < r0) || (r0 == 0 && cg + 1 == 0))) sc[jj][1] = -1e30f;
                    if (!(cg     < r1)) sc[jj][2] = -1e30f;
                    if (!(cg + 1 < r1)) sc[jj][3] = -1e30f;
                }
            }

            // ---- online softmax ----
            float mx0 = -1e30f, mx1 = -1e30f;
            #pragma unroll
            for (int jj = 0; jj < 8; jj++) {
                mx0 = fmaxf(mx0, fmaxf(sc[jj][0], sc[jj][1]));
                mx1 = fmaxf(mx1, fmaxf(sc[jj][2], sc[jj][3]));
            }
            mx0 = fmaxf(mx0, __shfl_xor_sync(0xffffffffu, mx0, 1));
            mx0 = fmaxf(mx0, __shfl_xor_sync(0xffffffffu, mx0, 2));
            mx1 = fmaxf(mx1, __shfl_xor_sync(0xffffffffu, mx1, 1));
            mx1 = fmaxf(mx1, __shfl_xor_sync(0xffffffffu, mx1, 2));
            const float mn0 = fmaxf(m0, mx0), mn1 = fmaxf(m1, mx1);
            const float a0 = __expf(m0 - mn0), a1 = __expf(m1 - mn1);
            float s0 = 0.f, s1 = 0.f;
            #pragma unroll
            for (int jj = 0; jj < 8; jj++) {
                sc[jj][0] = __expf(sc[jj][0] - mn0);
                sc[jj][1] = __expf(sc[jj][1] - mn0);
                sc[jj][2] = __expf(sc[jj][2] - mn1);
                sc[jj][3] = __expf(sc[jj][3] - mn1);
                s0 += sc[jj][0] + sc[jj][1];
                s1 += sc[jj][2] + sc[jj][3];
            }
            s0 += __shfl_xor_sync(0xffffffffu, s0, 1);
            s0 += __shfl_xor_sync(0xffffffffu, s0, 2);
            s1 += __shfl_xor_sync(0xffffffffu, s1, 1);
            s1 += __shfl_xor_sync(0xffffffffu, s1, 2);
            l0 = l0 * a0 + s0; l1 = l1 * a1 + s1;
            m0 = mn0; m1 = mn1;
            #pragma unroll
            for (int jj = 0; jj < 8; jj++) {
                o[jj][0] *= a0; o[jj][1] *= a0;
                o[jj][2] *= a1; o[jj][3] *= a1;
            }

            // ---- O += P @ V ----
            #pragma unroll
            for (int kk = 0; kk < 4; kk++) {
                uint32_t pf[4];
                pf[0] = h2pack(sc[2 * kk][0],     sc[2 * kk][1]);
                pf[1] = h2pack(sc[2 * kk][2],     sc[2 * kk][3]);
                pf[2] = h2pack(sc[2 * kk + 1][0], sc[2 * kk + 1][1]);
                pf[3] = h2pack(sc[2 * kk + 1][2], sc[2 * kk + 1][3]);
                uint32_t vf[4][4];
                #pragma unroll
                for (int jp = 0; jp < 4; jp++)
                    ldsm4t(vf[jp], vs + voff[jp] + kk * 16 * 144);
                #pragma unroll
                for (int jp = 0; jp < 4; jp++) {
                    mma_f16(o[2 * jp],     pf, &vf[jp][0]);
                    mma_f16(o[2 * jp + 1], pf, &vf[jp][2]);
                }
            }
        }
    }

    // ---- epilogue: normalize, convert to fp16 for Wo GEMM ----
    const float il0 = 1.f / l0, il1 = 1.f / l1;
    #pragma unroll
    for (int jj = 0; jj < 8; jj++) {
        const int col = jj * 8 + 2 * c;
        *(uint32_t*)&AH[rb + (size_t)qrow0 * E_ + col] =
            h2pack(o[jj][0] * il0, o[jj][1] * il0);
        *(uint32_t*)&AH[rb + (size_t)(qrow0 + 8) * E_ + col] =
            h2pack(o[jj][2] * il1, o[jj][3] * il1);
    }
}

// ===========================================================================
extern "C" void kernel_launch(void* const* d_in, const int* in_sizes, int n_in,
                              void* d_out, int out_size)
{
    const float* q  = (const float*)d_in[0];
    const float* k  = (const float*)d_in[1];
    const float* v  = (const float*)d_in[2];
    const float* Wq = (const float*)d_in[3];
    const float* Wk = (const float*)d_in[4];
    const float* Wv = (const float*)d_in[5];
    const float* bv = (const float*)d_in[6];
    const float* Wo = (const float*)d_in[7];
    const float* bo = (const float*)d_in[8];
    float* out = (float*)d_out;

    __half *qc, *kc, *vc, *wc, *qh, *kh, *vh, *ah;
    cudaGetSymbolAddress((void**)&qc, g_qc);
    cudaGetSymbolAddress((void**)&kc, g_kc);
    cudaGetSymbolAddress((void**)&vc, g_vc);
    cudaGetSymbolAddress((void**)&wc, g_wc);
    cudaGetSymbolAddress((void**)&qh, g_qh);
    cudaGetSymbolAddress((void**)&kh, g_kh);
    cudaGetSymbolAddress((void**)&vh, g_vh);
    cudaGetSymbolAddress((void**)&ah, g_ah);

    auto* gemm_qkv = gemm_t<128, 64, 4, 1, 3, 2>;   // 2-stage single-sync
    auto* gemm_wo  = gemm_t<64, 64, 2, 2, 4, 3>;    // 3-stage wait1
    cudaFuncSetAttribute(gemm_qkv, cudaFuncAttributeMaxDynamicSharedMemorySize,
                         QKV_SMEM);
    cudaFuncSetAttribute(gemm_wo, cudaFuncAttributeMaxDynamicSharedMemorySize,
                         WO_SMEM);
    cudaFuncSetAttribute(attn_mma, cudaFuncAttributeMaxDynamicSharedMemorySize,
                         ATTN_SMEM);

    // ---- fp16 conversion prepass (one launch) ----
    round_h_all<<<(TOT8 + 255) / 256, 256>>>(
        (const float4*)q, (const float4*)k, (const float4*)v,
        (const float4*)Wq, (const float4*)Wk, (const float4*)Wv, (const float4*)Wo,
        qc, kc, vc, wc);

    // ---- fused Q/K/V projections: 128x64 tiles (fp16 out) ----
    const dim3 gqkv(M_ / 128, E_ / 64, 3);     // (32, 16, 3) = 1536 tiles
    gemm_qkv<<<gqkv, 128, QKV_SMEM>>>(qc, kc, vc,
                                      wc, wc + (size_t)E_ * E_, wc + 2 * (size_t)E_ * E_,
                                      nullptr,
                                      qh, kh, vh,
                                      nullptr, nullptr, bv);

    // ---- attention (AQ=64, 4 CTAs/SM) ----
    const dim3 agrd(S_ / AQ, B_ * H_);         // (32, 32)
    attn_mma<<<agrd, 128, ATTN_SMEM>>>(qh, kh, vh, ah);

    // ---- output projection: 64x64 tiles, 3-stage (fp32 out + bias) ----
    const dim3 gwo(M_ / 64, E_ / 64, 1);       // (64, 16) = 1024 tiles
    gemm_wo<<<gwo, 128, WO_SMEM>>>(ah, ah, ah,
                                   wc + 3 * (size_t)E_ * E_, nullptr, nullptr,
                                   out,
                                   nullptr, nullptr, nullptr,
                                   bo, bo, bo);
}